// round 9
// baseline (speedup 1.0000x reference)
#include <cuda_runtime.h>
#include <cuda_bf16.h>
#include <math.h>
#include <cstdint>

// Problem constants
#define NN   307
#define TT   12
#define BB   128
#define DIN  2
#define DOUT 64
#define DE   10
#define NNP  320                  // padded node dim (k-dim for mma, mult of 16)

#define BND   (BB*NN*DOUT)        // 2,514,944
#define CURSZ (BB*TT*NN*DOUT)     // 30,179,328
#define BT    (BB*TT)             // 1536

// ---------------------------------------------------------------------------
// Device scratch
// ---------------------------------------------------------------------------
__device__ float g_Wg0[NN*132*128];
__device__ float g_Wu0[NN*132*64];
__device__ float g_Wg1[NN*256*128];
__device__ float g_Wu1[NN*256*64];
__device__ float g_bg0[NN*128];
__device__ float g_bu0[NN*64];
__device__ float g_bg1[NN*128];
__device__ float g_bu1[NN*64];

__device__ __nv_bfloat16 g_adjH[NNP*NNP];   // adj [n][m] bf16 hi plane, zero-padded
__device__ __nv_bfloat16 g_adjL[NNP*NNP];   // adj [n][m] bf16 lo plane

// per-layer state
__device__ float g_h0  [BND];
__device__ float g_zh0 [BND];
__device__ float g_r0  [BND];
__device__ float g_Gh0 [BND];
__device__ float g_Gzh0[BND];
__device__ float g_h1  [BND];
__device__ float g_zh1 [BND];
__device__ float g_r1  [BND];
__device__ float g_Gh1 [BND];
__device__ float g_Gzh1[BND];
__device__ float g_Gx1 [BND];         // adj @ seq0[t] (layer1, current t)

__device__ float g_Gx2 [BT*NN*DIN];   // adj @ x (layer0, all t) [B,T,N,2]
__device__ float g_seq0[CURSZ];       // layer0 output sequence [B,T,N,64]

__device__ __forceinline__ float sigm(float v) { return 1.0f / (1.0f + expf(-v)); }

// packed fp32x2 helpers
__device__ __forceinline__ unsigned long long pk2(float x, float y) {
    unsigned long long r;
    asm("mov.b64 %0, {%1, %2};" : "=l"(r) : "f"(x), "f"(y));
    return r;
}
__device__ __forceinline__ unsigned long long ffma2(unsigned long long a,
                                                    unsigned long long b,
                                                    unsigned long long c) {
    unsigned long long d;
    asm("fma.rn.f32x2 %0, %1, %2, %3;" : "=l"(d) : "l"(a), "l"(b), "l"(c));
    return d;
}
__device__ __forceinline__ void unpk2(unsigned long long v, float& lo, float& hi) {
    asm("mov.b64 {%0, %1}, %2;" : "=f"(lo), "=f"(hi) : "l"(v));
}

// bf16 mma.sync m16n8k16
__device__ __forceinline__ void mma_bf16(float* c, const uint32_t* a,
                                         uint32_t b0, uint32_t b1) {
    asm volatile(
        "mma.sync.aligned.m16n8k16.row.col.f32.bf16.bf16.f32 "
        "{%0,%1,%2,%3}, {%4,%5,%6,%7}, {%8,%9}, {%0,%1,%2,%3};"
        : "+f"(c[0]), "+f"(c[1]), "+f"(c[2]), "+f"(c[3])
        : "r"(a[0]), "r"(a[1]), "r"(a[2]), "r"(a[3]), "r"(b0), "r"(b1));
}

// ---------------------------------------------------------------------------
// prep kernels
// ---------------------------------------------------------------------------
#define S_WG0 (132*128)
#define S_WU0 (132*64)
#define S_WG1 (256*128)
#define S_WU1 (256*64)
#define C0 ((long)NN*S_WG0)
#define C1 (C0 + (long)NN*S_WU0)
#define C2 (C1 + (long)NN*S_WG1)
#define C3 (C2 + (long)NN*S_WU1)
#define C4 (C3 + (long)NN*128)
#define C5 (C4 + (long)NN*64)
#define C6 (C5 + (long)NN*128)
#define C7 (C6 + (long)NN*64)

__global__ void prep_all(const float* __restrict__ E,
                         const float* __restrict__ wg0, const float* __restrict__ wu0,
                         const float* __restrict__ wg1, const float* __restrict__ wu1,
                         const float* __restrict__ bg0, const float* __restrict__ bu0,
                         const float* __restrict__ bg1, const float* __restrict__ bu1) {
    long idx = (long)blockIdx.x * blockDim.x + threadIdx.x;
    if (idx >= C7) return;
    const float* pool; float* out; long loc; int S;
    if      (idx < C0) { pool = wg0; out = g_Wg0; loc = idx;      S = S_WG0; }
    else if (idx < C1) { pool = wu0; out = g_Wu0; loc = idx - C0; S = S_WU0; }
    else if (idx < C2) { pool = wg1; out = g_Wg1; loc = idx - C1; S = S_WG1; }
    else if (idx < C3) { pool = wu1; out = g_Wu1; loc = idx - C2; S = S_WU1; }
    else if (idx < C4) { pool = bg0; out = g_bg0; loc = idx - C3; S = 128;   }
    else if (idx < C5) { pool = bu0; out = g_bu0; loc = idx - C4; S = 64;    }
    else if (idx < C6) { pool = bg1; out = g_bg1; loc = idx - C5; S = 128;   }
    else               { pool = bu1; out = g_bu1; loc = idx - C6; S = 64;    }
    int n = (int)(loc / S);
    long j = loc - (long)n * S;
    float acc = 0.0f;
#pragma unroll
    for (int d = 0; d < DE; d++)
        acc += E[n*DE + d] * pool[(long)d*S + j];
    out[loc] = acc;
}

// adj -> bf16 hi/lo planes, [n][m] layout, zero-padded to 320x320
__global__ void prep_adjB(const float* __restrict__ adj) {
    int i = blockIdx.x * blockDim.x + threadIdx.x;
    if (i >= NNP*NNP) return;
    int n = i / NNP, m = i - n*NNP;
    float v = (n < NN && m < NN) ? adj[(long)n*NN + m] : 0.0f;
    __nv_bfloat16 h = __float2bfloat16(v);
    __nv_bfloat16 l = __float2bfloat16(v - __bfloat162float(h));
    g_adjH[i] = h;
    g_adjL[i] = l;
}

__global__ void init_h(const float* __restrict__ init, int l) {
    int i = blockIdx.x * blockDim.x + threadIdx.x;
    if (i < BND) {
        float v = init[(long)l*BND + i];
        if (l == 0) g_h0[i] = v; else g_h1[i] = v;
    }
}

// ---------------------------------------------------------------------------
// adj @ x for all timesteps (layer0, 2 channels): one launch, f32 (tiny)
// ---------------------------------------------------------------------------
__global__ void __launch_bounds__(256) graph_x2_all(const float* __restrict__ adj,
                                                    const float* __restrict__ x) {
    int n0  = blockIdx.x * 64;
    int bt0 = blockIdx.y * 64;
    int tid = threadIdx.x;
    int tx  = tid & 15;
    int ty  = tid >> 4;

    __shared__ float adjs[32][65];
    __shared__ float xs[64][65];

    float acc[4][4][2] = {};

    for (int m0 = 0; m0 < NN; m0 += 32) {
#pragma unroll
        for (int j = 0; j < 8; j++) {
            int lin = tid + j*256;
            int nl = lin >> 5, ml = lin & 31;
            int n = n0 + nl, m = m0 + ml;
            adjs[ml][nl] = (n < NN && m < NN) ? adj[(long)n*NN + m] : 0.0f;
        }
#pragma unroll
        for (int j = 0; j < 16; j++) {
            int lin = tid + j*256;
            int mc = lin & 63;
            int bt = lin >> 6;
            int m = m0 + (mc >> 1);
            xs[mc][bt] = (m < NN) ? x[((long)(bt0 + bt)*NN + m)*2 + (mc & 1)] : 0.0f;
        }
        __syncthreads();
#pragma unroll
        for (int ml = 0; ml < 32; ml++) {
            float a0 = adjs[ml][ty*4+0];
            float a1 = adjs[ml][ty*4+1];
            float a2 = adjs[ml][ty*4+2];
            float a3 = adjs[ml][ty*4+3];
#pragma unroll
            for (int jj = 0; jj < 4; jj++) {
                float x0 = xs[ml*2+0][tx*4+jj];
                float x1 = xs[ml*2+1][tx*4+jj];
                acc[0][jj][0] += a0*x0; acc[0][jj][1] += a0*x1;
                acc[1][jj][0] += a1*x0; acc[1][jj][1] += a1*x1;
                acc[2][jj][0] += a2*x0; acc[2][jj][1] += a2*x1;
                acc[3][jj][0] += a3*x0; acc[3][jj][1] += a3*x1;
            }
        }
        __syncthreads();
    }
#pragma unroll
    for (int i = 0; i < 4; i++) {
        int n = n0 + ty*4 + i;
        if (n >= NN) continue;
#pragma unroll
        for (int jj = 0; jj < 4; jj++) {
            int bt = bt0 + tx*4 + jj;
            *(float2*)&g_Gx2[((long)bt*NN + n)*2] =
                make_float2(acc[i][jj][0], acc[i][jj][1]);
        }
    }
}

// ---------------------------------------------------------------------------
// Merged graph propagation (bf16 split mma). Super-step s pipelines layers:
//   stage==0 (pre-gate):  z=0: Gh0=adj@h0 (s<TT)
//                         z=1: Gh1=adj@h1 (s>=1)
//                         z=2: Gx1=adj@seq0[s-1] (s>=1)
//   stage==1 (pre-cand):  z=0: Gzh0=adj@zh0 (s<TT)
//                         z=1: Gzh1=adj@zh1 (s>=1)
// Per block: 64 nodes x 64 channels x 1 batch; 8 warps as 4(m16) x 2(n32).
// ---------------------------------------------------------------------------
__global__ void __launch_bounds__(256) graph_merged(int s, int stage) {
    int z = blockIdx.z;
    const float* src; float* dst;
    long sstride = (long)NN*DOUT;
    if (stage == 0) {
        if (z == 0)      { if (s >= TT) return; src = g_h0; dst = g_Gh0; }
        else if (z == 1) { if (s < 1)  return; src = g_h1; dst = g_Gh1; }
        else             { if (s < 1)  return;
                           src = g_seq0 + (long)(s-1)*NN*DOUT;
                           sstride = (long)TT*NN*DOUT; dst = g_Gx1; }
    } else {
        if (z == 0)      { if (s >= TT) return; src = g_zh0; dst = g_Gzh0; }
        else             { if (s < 1)  return; src = g_zh1; dst = g_Gzh1; }
    }

    int n0  = blockIdx.x * 64;
    int b   = blockIdx.y;
    int tid = threadIdx.x;
    int lane = tid & 31;
    int wid  = tid >> 5;
    int wm = wid & 3;            // m16 tile: rows n0 + wm*16
    int wn = wid >> 2;           // n32 tile: cols wn*32

    __shared__ __nv_bfloat16 Ah[64][20], Al[64][20];   // A: [n][m16]
    __shared__ __nv_bfloat16 Bh[64][20], Bl[64][20];   // B: [c][m16]

    float acc[4][4];
#pragma unroll
    for (int i = 0; i < 4; i++)
#pragma unroll
        for (int j = 0; j < 4; j++) acc[i][j] = 0.0f;

    const float* sb = src + (long)b * sstride;
    int a_nl = tid >> 2;         // A fill: row (64 rows x 4 quads)
    int a_kq = tid & 3;
    int b_c4 = (tid & 15) * 4;   // B fill: 4 consecutive channels
    int b_ml = tid >> 4;         // B fill: k row (16)

    for (int m0 = 0; m0 < NNP; m0 += 16) {
        // A fill: u64 = 4 bf16 per plane per thread
        {
            long so = (long)(n0 + a_nl)*NNP + m0 + a_kq*4;
            *(uint64_t*)&Ah[a_nl][a_kq*4] = *(const uint64_t*)&g_adjH[so];
            *(uint64_t*)&Al[a_nl][a_kq*4] = *(const uint64_t*)&g_adjL[so];
        }
        // B fill: one float4 load, split, 4 column stores per plane
        {
            int m = m0 + b_ml;
            float4 v = make_float4(0.f, 0.f, 0.f, 0.f);
            if (m < NN) v = *(const float4*)&sb[(long)m*DOUT + b_c4];
            float vv[4] = {v.x, v.y, v.z, v.w};
#pragma unroll
            for (int i = 0; i < 4; i++) {
                __nv_bfloat16 h = __float2bfloat16(vv[i]);
                __nv_bfloat16 l = __float2bfloat16(vv[i] - __bfloat162float(h));
                Bh[b_c4 + i][b_ml] = h;
                Bl[b_c4 + i][b_ml] = l;
            }
        }
        __syncthreads();

        uint32_t a_h[4], a_l[4];
#pragma unroll
        for (int j = 0; j < 4; j++) {
            int row = wm*16 + (lane >> 2) + (j & 1)*8;
            int kp  = (lane & 3)*2 + (j & 2)*4;
            a_h[j] = *(const uint32_t*)&Ah[row][kp];
            a_l[j] = *(const uint32_t*)&Al[row][kp];
        }
#pragma unroll
        for (int tn = 0; tn < 4; tn++) {
            int cc  = wn*32 + tn*8 + (lane >> 2);
            int k0p = (lane & 3)*2;
            uint32_t b_h0 = *(const uint32_t*)&Bh[cc][k0p];
            uint32_t b_h1 = *(const uint32_t*)&Bh[cc][k0p + 8];
            uint32_t b_l0 = *(const uint32_t*)&Bl[cc][k0p];
            uint32_t b_l1 = *(const uint32_t*)&Bl[cc][k0p + 8];
            mma_bf16(acc[tn], a_h, b_h0, b_h1);
            mma_bf16(acc[tn], a_h, b_l0, b_l1);
            mma_bf16(acc[tn], a_l, b_h0, b_h1);
        }
        __syncthreads();
    }

    long db = (long)b * NN * DOUT;
#pragma unroll
    for (int tn = 0; tn < 4; tn++) {
        int n = n0 + wm*16 + (lane >> 2);
        int c = wn*32 + tn*8 + (lane & 3)*2;
        if (n < NN)
            *(float2*)&dst[db + (long)n*DOUT + c] =
                make_float2(acc[tn][0], acc[tn][1]);
        if (n + 8 < NN)
            *(float2*)&dst[db + (long)(n + 8)*DOUT + c] =
                make_float2(acc[tn][2], acc[tn][3]);
    }
}

// ---------------------------------------------------------------------------
// A-row gather: A[b, kk] = [ x(CIN) | h_or_zh(64) | Gx(CIN) | Gh_or_Gzh(64) ]
// ---------------------------------------------------------------------------
template<int CIN, int MODE>
__device__ __forceinline__ float gatherA(const float* __restrict__ xext,
                                         int b, int n, int t, int kk) {
    long hoff = ((long)b*NN + n)*64;
    if (CIN == 2) {
        if (kk >= 132) return 0.0f;
        long xoff = ((long)b*TT + t)*NN*2 + (long)n*2;
        if (kk < 2)   return xext[xoff + kk];
        if (kk < 66)  return (MODE ? g_zh0 : g_h0)[hoff + (kk - 2)];
        if (kk < 68)  return g_Gx2[xoff + (kk - 66)];
        return (MODE ? g_Gzh0 : g_Gh0)[hoff + (kk - 68)];
    } else {
        long xoff = ((long)b*TT + t)*NN*64 + (long)n*64;
        if (kk < 64)  return g_seq0[xoff + kk];
        if (kk < 128) return (MODE ? g_zh1 : g_h1)[hoff + (kk - 64)];
        if (kk < 192) return g_Gx1[hoff + (kk - 128)];
        return (MODE ? g_Gzh1 : g_Gh1)[hoff + (kk - 192)];
    }
}

// ---------------------------------------------------------------------------
// Gate GEMM body: tile 64b x 64o, 128 threads, 8b x 4o per thread. A as [kk][b].
// ---------------------------------------------------------------------------
template<int CIN>
__device__ __forceinline__ void gate_body(const float* __restrict__ xext, int t,
                                          int n, int bh, int oh,
                                          float (*As)[68], float (*Ws)[68]) {
    constexpr int KD  = 2*CIN + 2*DOUT;
    constexpr int NKT = (KD + 31) / 32;
    const float* W    = (CIN == 2) ? g_Wg0 : g_Wg1;
    const float* bias = (CIN == 2) ? g_bg0 : g_bg1;
    const float* hbuf = (CIN == 2) ? g_h0  : g_h1;
    float* zhbuf      = (CIN == 2) ? g_zh0 : g_zh1;
    float* rbuf       = (CIN == 2) ? g_r0  : g_r1;

    int tid = threadIdx.x;
    int tx = tid & 15;
    int ty = tid >> 4;

    unsigned long long acc2[8][2];
#pragma unroll
    for (int i = 0; i < 8; i++) { acc2[i][0] = 0ull; acc2[i][1] = 0ull; }

    for (int kt = 0; kt < NKT; kt++) {
        int k0 = kt * 32;
#pragma unroll
        for (int j = 0; j < 16; j++) {
            int lin = tid + j*128;
            int kl = lin & 31;
            int b  = lin >> 5;
            As[kl][b] = gatherA<CIN,0>(xext, bh*64 + b, n, t, k0 + kl);
        }
#pragma unroll
        for (int j = 0; j < 4; j++) {
            int lin = tid + j*128;
            int c4  = lin & 15;
            int row = lin >> 4;
            int kk = k0 + row;
            float4 v = make_float4(0.f, 0.f, 0.f, 0.f);
            if (kk < KD)
                v = *(const float4*)&W[((long)n*KD + kk)*128 + oh*64 + c4*4];
            *(float4*)&Ws[row][c4*4] = v;
        }
        __syncthreads();
#pragma unroll
        for (int k = 0; k < 32; k++) {
            float4 aLo = *(const float4*)&As[k][ty*8];
            float4 aHi = *(const float4*)&As[k][ty*8 + 4];
            ulonglong2 w2 = *(const ulonglong2*)&Ws[k][tx*4];
            float av[8] = {aLo.x, aLo.y, aLo.z, aLo.w,
                           aHi.x, aHi.y, aHi.z, aHi.w};
#pragma unroll
            for (int i = 0; i < 8; i++) {
                unsigned long long ad = pk2(av[i], av[i]);
                acc2[i][0] = ffma2(ad, w2.x, acc2[i][0]);
                acc2[i][1] = ffma2(ad, w2.y, acc2[i][1]);
            }
        }
        __syncthreads();
    }

    float4 bv = *(const float4*)&bias[n*128 + oh*64 + tx*4];
#pragma unroll
    for (int i = 0; i < 8; i++) {
        int b = bh*64 + ty*8 + i;
        long hb = ((long)b*NN + n)*64 + tx*4;
        float v0, v1, v2, v3;
        unpk2(acc2[i][0], v0, v1);
        unpk2(acc2[i][1], v2, v3);
        v0 = sigm(v0 + bv.x); v1 = sigm(v1 + bv.y);
        v2 = sigm(v2 + bv.z); v3 = sigm(v3 + bv.w);
        if (oh == 0) {
            float4 hv = *(const float4*)&hbuf[hb];
            *(float4*)&zhbuf[hb] = make_float4(v0*hv.x, v1*hv.y, v2*hv.z, v3*hv.w);
        } else {
            *(float4*)&rbuf[hb] = make_float4(v0, v1, v2, v3);
        }
    }
}

// Merged gate: z = layer*2 + oh
__global__ void __launch_bounds__(128, 8) gate_merged(const float* __restrict__ x, int s) {
    __shared__ float As[32][68];
    __shared__ float Ws[32][68];
    int zz = blockIdx.z;
    if (zz < 2) {
        if (s >= TT) return;
        gate_body<2>(x, s, blockIdx.x, blockIdx.y, zz, As, Ws);
    } else {
        if (s < 1) return;
        gate_body<64>(nullptr, s - 1, blockIdx.x, blockIdx.y, zz - 2, As, Ws);
    }
}

// ---------------------------------------------------------------------------
// Candidate GEMM body (NO=64) + GRU update.
// ---------------------------------------------------------------------------
template<int CIN>
__device__ __forceinline__ void cand_body(const float* __restrict__ xext, int t,
                                          int n, int bh,
                                          float* __restrict__ curOut,
                                          float* __restrict__ lastOut,
                                          float (*As)[68], float (*Ws)[68]) {
    constexpr int KD  = 2*CIN + 2*DOUT;
    constexpr int NKT = (KD + 31) / 32;
    const float* W    = (CIN == 2) ? g_Wu0 : g_Wu1;
    const float* bias = (CIN == 2) ? g_bu0 : g_bu1;
    float* hbuf       = (CIN == 2) ? g_h0  : g_h1;
    const float* rbuf = (CIN == 2) ? g_r0  : g_r1;

    int tid = threadIdx.x;
    int tx = tid & 15;
    int ty = tid >> 4;

    unsigned long long acc2[8][2];
#pragma unroll
    for (int i = 0; i < 8; i++) { acc2[i][0] = 0ull; acc2[i][1] = 0ull; }

    for (int kt = 0; kt < NKT; kt++) {
        int k0 = kt * 32;
#pragma unroll
        for (int j = 0; j < 16; j++) {
            int lin = tid + j*128;
            int kl = lin & 31;
            int b  = lin >> 5;
            As[kl][b] = gatherA<CIN,1>(xext, bh*64 + b, n, t, k0 + kl);
        }
#pragma unroll
        for (int j = 0; j < 4; j++) {
            int lin = tid + j*128;
            int c4  = lin & 15;
            int row = lin >> 4;
            int kk = k0 + row;
            float4 v = make_float4(0.f, 0.f, 0.f, 0.f);
            if (kk < KD)
                v = *(const float4*)&W[((long)n*KD + kk)*64 + c4*4];
            *(float4*)&Ws[row][c4*4] = v;
        }
        __syncthreads();
#pragma unroll
        for (int k = 0; k < 32; k++) {
            float4 aLo = *(const float4*)&As[k][ty*8];
            float4 aHi = *(const float4*)&As[k][ty*8 + 4];
            ulonglong2 w2 = *(const ulonglong2*)&Ws[k][tx*4];
            float av[8] = {aLo.x, aLo.y, aLo.z, aLo.w,
                           aHi.x, aHi.y, aHi.z, aHi.w};
#pragma unroll
            for (int i = 0; i < 8; i++) {
                unsigned long long ad = pk2(av[i], av[i]);
                acc2[i][0] = ffma2(ad, w2.x, acc2[i][0]);
                acc2[i][1] = ffma2(ad, w2.y, acc2[i][1]);
            }
        }
        __syncthreads();
    }

    float4 bv = *(const float4*)&bias[n*64 + tx*4];
#pragma unroll
    for (int i = 0; i < 8; i++) {
        int b = bh*64 + ty*8 + i;
        long hb = ((long)b*NN + n)*64 + tx*4;
        float c0, c1, c2, c3;
        unpk2(acc2[i][0], c0, c1);
        unpk2(acc2[i][1], c2, c3);
        c0 = tanhf(c0 + bv.x); c1 = tanhf(c1 + bv.y);
        c2 = tanhf(c2 + bv.z); c3 = tanhf(c3 + bv.w);
        float4 rv = *(const float4*)&rbuf[hb];
        float4 hv = *(const float4*)&hbuf[hb];
        float4 o;
        o.x = rv.x*hv.x + (1.0f - rv.x)*c0;
        o.y = rv.y*hv.y + (1.0f - rv.y)*c1;
        o.z = rv.z*hv.z + (1.0f - rv.z)*c2;
        o.w = rv.w*hv.w + (1.0f - rv.w)*c3;
        *(float4*)&hbuf[hb] = o;
        float* seq = (CIN == 2) ? g_seq0 : curOut;
        *(float4*)&seq[((long)(b*TT + t))*NN*DOUT + (long)n*DOUT + tx*4] = o;
        if (lastOut) *(float4*)&lastOut[hb] = o;
    }
}

// Merged candidate: z = layer
__global__ void __launch_bounds__(128, 8) cand_merged(const float* __restrict__ x, int s,
                                                      float* __restrict__ out,
                                                      float* __restrict__ lastBase) {
    __shared__ float As[32][68];
    __shared__ float Ws[32][68];
    int layer = blockIdx.z;
    if (layer == 0) {
        if (s >= TT) return;
        cand_body<2>(x, s, blockIdx.x, blockIdx.y, nullptr,
                     (s == TT-1) ? lastBase : nullptr, As, Ws);
    } else {
        if (s < 1) return;
        cand_body<64>(nullptr, s - 1, blockIdx.x, blockIdx.y, out,
                      (s == TT) ? lastBase + BND : nullptr, As, Ws);
    }
}

// ---------------------------------------------------------------------------
// Host driver — single stream, software-pipelined super-steps.
// ---------------------------------------------------------------------------
extern "C" void kernel_launch(void* const* d_in, const int* in_sizes, int n_in,
                              void* d_out, int out_size) {
    const float* x    = (const float*)d_in[0];
    const float* init = (const float*)d_in[1];
    const float* E    = (const float*)d_in[2];
    const float* adj  = (const float*)d_in[3];
    const float* wg0  = (const float*)d_in[4];
    const float* bg0  = (const float*)d_in[5];
    const float* wu0  = (const float*)d_in[6];
    const float* bu0  = (const float*)d_in[7];
    const float* wg1  = (const float*)d_in[8];
    const float* bg1  = (const float*)d_in[9];
    const float* wu1  = (const float*)d_in[10];
    const float* bu1  = (const float*)d_in[11];

    float* out      = (float*)d_out;
    float* lastBase = out + (long)CURSZ;

    // prelude (5 launches -> ncu slot 5 = first graph_merged)
    prep_all<<<(unsigned)((C7 + 255) / 256), 256>>>(E, wg0, wu0, wg1, wu1,
                                                    bg0, bu0, bg1, bu1);
    prep_adjB<<<(NNP*NNP + 255) / 256, 256>>>(adj);
    init_h<<<(BND + 255) / 256, 256>>>(init, 0);
    init_h<<<(BND + 255) / 256, 256>>>(init, 1);
    graph_x2_all<<<dim3(5, BT/64), 256>>>(adj, x);

    // 13 super-steps: layer0 @ t=s, layer1 @ t=s-1
    for (int s = 0; s <= TT; s++) {
        graph_merged<<<dim3(5, BB, 3), 256>>>(s, 0);          // Gh0, Gh1, Gx1
        gate_merged<<<dim3(NN, 2, 4), 128>>>(x, s);           // z/r both layers
        graph_merged<<<dim3(5, BB, 2), 256>>>(s, 1);          // Gzh0, Gzh1
        cand_merged<<<dim3(NN, 2, 2), 128>>>(x, s, out, lastBase);
    }
}

// round 10
// speedup vs baseline: 1.1704x; 1.1704x over previous
#include <cuda_runtime.h>
#include <cuda_bf16.h>
#include <math.h>
#include <cstdint>

// Problem constants
#define NN   307
#define TT   12
#define BB   128
#define DIN  2
#define DOUT 64
#define DE   10
#define NNP  320                  // padded node dim (k-dim for mma, mult of 16)

#define BND   (BB*NN*DOUT)        // 2,514,944
#define CURSZ (BB*TT*NN*DOUT)     // 30,179,328
#define BT    (BB*TT)             // 1536

// ---------------------------------------------------------------------------
// Device scratch
// ---------------------------------------------------------------------------
__device__ float g_Wg0[NN*132*128];
__device__ float g_Wu0[NN*132*64];
__device__ float g_Wg1[NN*256*128];
__device__ float g_Wu1[NN*256*64];
__device__ float g_bg0[NN*128];
__device__ float g_bu0[NN*64];
__device__ float g_bg1[NN*128];
__device__ float g_bu1[NN*64];

__device__ __nv_bfloat16 g_adjH[NNP*NNP];   // adj [n][m] bf16 hi plane, zero-padded
__device__ __nv_bfloat16 g_adjL[NNP*NNP];   // adj [n][m] bf16 lo plane

// per-layer state (layer 0 and layer 1 run concurrently on separate streams)
__device__ float g_h0  [BND];
__device__ float g_zh0 [BND];
__device__ float g_r0  [BND];
__device__ float g_Gh0 [BND];
__device__ float g_Gzh0[BND];
__device__ float g_h1  [BND];
__device__ float g_zh1 [BND];
__device__ float g_r1  [BND];
__device__ float g_Gh1 [BND];
__device__ float g_Gzh1[BND];

__device__ float g_Gx2 [BT*NN*DIN];   // adj @ x (layer0, all t) [B,T,N,2]
__device__ float g_Gxall[CURSZ];      // adj @ seq0[t] for all t [B,T,N,64]
__device__ float g_seq0[CURSZ];       // layer0 output sequence [B,T,N,64]

__device__ __forceinline__ float sigm(float v) { return 1.0f / (1.0f + expf(-v)); }

// packed fp32x2 helpers (GEMMs)
__device__ __forceinline__ unsigned long long pk2(float x, float y) {
    unsigned long long r;
    asm("mov.b64 %0, {%1, %2};" : "=l"(r) : "f"(x), "f"(y));
    return r;
}
__device__ __forceinline__ unsigned long long ffma2(unsigned long long a,
                                                    unsigned long long b,
                                                    unsigned long long c) {
    unsigned long long d;
    asm("fma.rn.f32x2 %0, %1, %2, %3;" : "=l"(d) : "l"(a), "l"(b), "l"(c));
    return d;
}
__device__ __forceinline__ void unpk2(unsigned long long v, float& lo, float& hi) {
    asm("mov.b64 {%0, %1}, %2;" : "=f"(lo), "=f"(hi) : "l"(v));
}

// bf16 mma.sync m16n8k16
__device__ __forceinline__ void mma_bf16(float* c, const uint32_t* a,
                                         uint32_t b0, uint32_t b1) {
    asm volatile(
        "mma.sync.aligned.m16n8k16.row.col.f32.bf16.bf16.f32 "
        "{%0,%1,%2,%3}, {%4,%5,%6,%7}, {%8,%9}, {%0,%1,%2,%3};"
        : "+f"(c[0]), "+f"(c[1]), "+f"(c[2]), "+f"(c[3])
        : "r"(a[0]), "r"(a[1]), "r"(a[2]), "r"(a[3]), "r"(b0), "r"(b1));
}

// ---------------------------------------------------------------------------
// prep kernels
// ---------------------------------------------------------------------------
#define S_WG0 (132*128)
#define S_WU0 (132*64)
#define S_WG1 (256*128)
#define S_WU1 (256*64)
#define C0 ((long)NN*S_WG0)
#define C1 (C0 + (long)NN*S_WU0)
#define C2 (C1 + (long)NN*S_WG1)
#define C3 (C2 + (long)NN*S_WU1)
#define C4 (C3 + (long)NN*128)
#define C5 (C4 + (long)NN*64)
#define C6 (C5 + (long)NN*128)
#define C7 (C6 + (long)NN*64)

__global__ void prep_all(const float* __restrict__ E,
                         const float* __restrict__ wg0, const float* __restrict__ wu0,
                         const float* __restrict__ wg1, const float* __restrict__ wu1,
                         const float* __restrict__ bg0, const float* __restrict__ bu0,
                         const float* __restrict__ bg1, const float* __restrict__ bu1) {
    long idx = (long)blockIdx.x * blockDim.x + threadIdx.x;
    if (idx >= C7) return;
    const float* pool; float* out; long loc; int S;
    if      (idx < C0) { pool = wg0; out = g_Wg0; loc = idx;      S = S_WG0; }
    else if (idx < C1) { pool = wu0; out = g_Wu0; loc = idx - C0; S = S_WU0; }
    else if (idx < C2) { pool = wg1; out = g_Wg1; loc = idx - C1; S = S_WG1; }
    else if (idx < C3) { pool = wu1; out = g_Wu1; loc = idx - C2; S = S_WU1; }
    else if (idx < C4) { pool = bg0; out = g_bg0; loc = idx - C3; S = 128;   }
    else if (idx < C5) { pool = bu0; out = g_bu0; loc = idx - C4; S = 64;    }
    else if (idx < C6) { pool = bg1; out = g_bg1; loc = idx - C5; S = 128;   }
    else               { pool = bu1; out = g_bu1; loc = idx - C6; S = 64;    }
    int n = (int)(loc / S);
    long j = loc - (long)n * S;
    float acc = 0.0f;
#pragma unroll
    for (int d = 0; d < DE; d++)
        acc += E[n*DE + d] * pool[(long)d*S + j];
    out[loc] = acc;
}

// adj -> bf16 hi/lo planes, [n][m] layout, zero-padded to 320x320
__global__ void prep_adjB(const float* __restrict__ adj) {
    int i = blockIdx.x * blockDim.x + threadIdx.x;
    if (i >= NNP*NNP) return;
    int n = i / NNP, m = i - n*NNP;
    float v = (n < NN && m < NN) ? adj[(long)n*NN + m] : 0.0f;
    __nv_bfloat16 h = __float2bfloat16(v);
    __nv_bfloat16 l = __float2bfloat16(v - __bfloat162float(h));
    g_adjH[i] = h;
    g_adjL[i] = l;
}

__global__ void init_h(const float* __restrict__ init, int l) {
    int i = blockIdx.x * blockDim.x + threadIdx.x;
    if (i < BND) {
        float v = init[(long)l*BND + i];
        if (l == 0) g_h0[i] = v; else g_h1[i] = v;
    }
}

// ---------------------------------------------------------------------------
// adj @ x for all timesteps (layer0, 2 channels): one launch, f32 (tiny)
// ---------------------------------------------------------------------------
__global__ void __launch_bounds__(256) graph_x2_all(const float* __restrict__ adj,
                                                    const float* __restrict__ x) {
    int n0  = blockIdx.x * 64;
    int bt0 = blockIdx.y * 64;
    int tid = threadIdx.x;
    int tx  = tid & 15;
    int ty  = tid >> 4;

    __shared__ float adjs[32][65];
    __shared__ float xs[64][65];

    float acc[4][4][2] = {};

    for (int m0 = 0; m0 < NN; m0 += 32) {
#pragma unroll
        for (int j = 0; j < 8; j++) {
            int lin = tid + j*256;
            int nl = lin >> 5, ml = lin & 31;
            int n = n0 + nl, m = m0 + ml;
            adjs[ml][nl] = (n < NN && m < NN) ? adj[(long)n*NN + m] : 0.0f;
        }
#pragma unroll
        for (int j = 0; j < 16; j++) {
            int lin = tid + j*256;
            int mc = lin & 63;
            int bt = lin >> 6;
            int m = m0 + (mc >> 1);
            xs[mc][bt] = (m < NN) ? x[((long)(bt0 + bt)*NN + m)*2 + (mc & 1)] : 0.0f;
        }
        __syncthreads();
#pragma unroll
        for (int ml = 0; ml < 32; ml++) {
            float a0 = adjs[ml][ty*4+0];
            float a1 = adjs[ml][ty*4+1];
            float a2 = adjs[ml][ty*4+2];
            float a3 = adjs[ml][ty*4+3];
#pragma unroll
            for (int jj = 0; jj < 4; jj++) {
                float x0 = xs[ml*2+0][tx*4+jj];
                float x1 = xs[ml*2+1][tx*4+jj];
                acc[0][jj][0] += a0*x0; acc[0][jj][1] += a0*x1;
                acc[1][jj][0] += a1*x0; acc[1][jj][1] += a1*x1;
                acc[2][jj][0] += a2*x0; acc[2][jj][1] += a2*x1;
                acc[3][jj][0] += a3*x0; acc[3][jj][1] += a3*x1;
            }
        }
        __syncthreads();
    }
#pragma unroll
    for (int i = 0; i < 4; i++) {
        int n = n0 + ty*4 + i;
        if (n >= NN) continue;
#pragma unroll
        for (int jj = 0; jj < 4; jj++) {
            int bt = bt0 + tx*4 + jj;
            *(float2*)&g_Gx2[((long)bt*NN + n)*2] =
                make_float2(acc[i][jj][0], acc[i][jj][1]);
        }
    }
}

// ---------------------------------------------------------------------------
// Graph propagation via bf16 split mma, 2 batches per block, permuted-k smem.
// Row layout (20 halves/row, 40B): original khalf h -> pos p(h):
//   h<8:  p = (h>>1)*4 + (h&1)      h>=8: p = ((h-8)>>1)*4 + 2 + (h&1)
// so a lane's two k-octet u32 frags sit in ONE u64 at byte (lane&3)*8.
// Block: 64n x 64c x 2b; 8 warps = 4(m16) x 2(n32). grid (5, 64).
// srcsel: 0=h0, 1=zh0, 2=seq0[t], 3=h1, 4=zh1
// dstsel: 0=Gh0, 1=Gzh0, 2=Gxall[t], 3=Gh1, 4=Gzh1
// ---------------------------------------------------------------------------
__global__ void __launch_bounds__(256) graph64_mma(int srcsel, int t, int dstsel) {
    const float* src; long sstride = (long)NN*DOUT;
    switch (srcsel) {
        case 0:  src = g_h0;  break;
        case 1:  src = g_zh0; break;
        case 2:  src = g_seq0 + (long)t*NN*DOUT; sstride = (long)TT*NN*DOUT; break;
        case 3:  src = g_h1;  break;
        default: src = g_zh1; break;
    }
    float* dst; long dstride = (long)NN*DOUT;
    switch (dstsel) {
        case 0:  dst = g_Gh0;  break;
        case 1:  dst = g_Gzh0; break;
        case 2:  dst = g_Gxall + (long)t*NN*DOUT; dstride = (long)TT*NN*DOUT; break;
        case 3:  dst = g_Gh1;  break;
        default: dst = g_Gzh1; break;
    }

    int n0  = blockIdx.x * 64;
    int b0  = blockIdx.y * 2;
    int tid = threadIdx.x;
    int lane = tid & 31;
    int wid  = tid >> 5;
    int wm = wid & 3;
    int wn = wid >> 2;

    __shared__ __nv_bfloat16 Ah[64][20], Al[64][20];
    __shared__ __nv_bfloat16 Bh[2][64][20], Bl[2][64][20];

    float acc[2][4][4];
#pragma unroll
    for (int w = 0; w < 2; w++)
#pragma unroll
        for (int i = 0; i < 4; i++)
#pragma unroll
            for (int j = 0; j < 4; j++) acc[w][i][j] = 0.0f;

    const float* sb0 = src + (long)b0 * sstride;
    const float* sb1 = src + (long)(b0+1) * sstride;

    for (int m0 = 0; m0 < NNP; m0 += 16) {
        // A fill: 512 (row,kp) u32 per plane, 2 per thread per plane
#pragma unroll
        for (int it = 0; it < 2; it++) {
            int idx = tid + it*256;
            int row = idx >> 3, kp = idx & 7;
            int off = (kp < 4) ? kp*8 : (kp-4)*8 + 4;
            long so = (long)(n0 + row)*NNP + m0 + kp*2;
            *(uint32_t*)((char*)&Ah[row][0] + off) = *(const uint32_t*)&g_adjH[so];
            *(uint32_t*)((char*)&Al[row][0] + off) = *(const uint32_t*)&g_adjL[so];
        }
        // B fill: 1024 tasks (w,c,kp), 4 per thread; split f32 -> hi/lo pair
#pragma unroll
        for (int it = 0; it < 4; it++) {
            int idx = tid + it*256;
            int c  = idx & 63;
            int kp = (idx >> 6) & 7;
            int w  = idx >> 9;
            const float* sb = w ? sb1 : sb0;
            int m = m0 + kp*2;
            float v0 = (m < NN)     ? sb[(long)m*DOUT + c]     : 0.0f;
            float v1 = (m + 1 < NN) ? sb[(long)(m+1)*DOUT + c] : 0.0f;
            __nv_bfloat16 h0 = __float2bfloat16(v0);
            __nv_bfloat16 l0 = __float2bfloat16(v0 - __bfloat162float(h0));
            __nv_bfloat16 h1 = __float2bfloat16(v1);
            __nv_bfloat16 l1 = __float2bfloat16(v1 - __bfloat162float(h1));
            int off = (kp < 4) ? kp*8 : (kp-4)*8 + 4;
            uint32_t hp, lp;
            {   // pack 2 bf16 into u32
                uint16_t h0b = *(uint16_t*)&h0, h1b = *(uint16_t*)&h1;
                uint16_t l0b = *(uint16_t*)&l0, l1b = *(uint16_t*)&l1;
                hp = (uint32_t)h0b | ((uint32_t)h1b << 16);
                lp = (uint32_t)l0b | ((uint32_t)l1b << 16);
            }
            *(uint32_t*)((char*)&Bh[w][c][0] + off) = hp;
            *(uint32_t*)((char*)&Bl[w][c][0] + off) = lp;
        }
        __syncthreads();

        // A frags: 4 x LDS.64
        int r  = wm*16 + (lane >> 2);
        int jb = (lane & 3) * 8;
        uint64_t A0h = *(const uint64_t*)((const char*)&Ah[r][0]   + jb);
        uint64_t A1h = *(const uint64_t*)((const char*)&Ah[r+8][0] + jb);
        uint64_t A0l = *(const uint64_t*)((const char*)&Al[r][0]   + jb);
        uint64_t A1l = *(const uint64_t*)((const char*)&Al[r+8][0] + jb);
        uint32_t a_h[4] = {(uint32_t)A0h, (uint32_t)A1h,
                           (uint32_t)(A0h >> 32), (uint32_t)(A1h >> 32)};
        uint32_t a_l[4] = {(uint32_t)A0l, (uint32_t)A1l,
                           (uint32_t)(A0l >> 32), (uint32_t)(A1l >> 32)};

#pragma unroll
        for (int tn = 0; tn < 4; tn++) {
            int cc = wn*32 + tn*8 + (lane >> 2);
#pragma unroll
            for (int w = 0; w < 2; w++) {
                uint64_t Bhv = *(const uint64_t*)((const char*)&Bh[w][cc][0] + jb);
                uint64_t Blv = *(const uint64_t*)((const char*)&Bl[w][cc][0] + jb);
                mma_bf16(acc[w][tn], a_h, (uint32_t)Bhv, (uint32_t)(Bhv >> 32));
                mma_bf16(acc[w][tn], a_h, (uint32_t)Blv, (uint32_t)(Blv >> 32));
                mma_bf16(acc[w][tn], a_l, (uint32_t)Bhv, (uint32_t)(Bhv >> 32));
            }
        }
        __syncthreads();
    }

    // Epilogue
#pragma unroll
    for (int w = 0; w < 2; w++) {
        long db = (long)(b0 + w) * dstride;
#pragma unroll
        for (int tn = 0; tn < 4; tn++) {
            int n = n0 + wm*16 + (lane >> 2);
            int c = wn*32 + tn*8 + (lane & 3)*2;
            if (n < NN)
                *(float2*)&dst[db + (long)n*DOUT + c] =
                    make_float2(acc[w][tn][0], acc[w][tn][1]);
            if (n + 8 < NN)
                *(float2*)&dst[db + (long)(n + 8)*DOUT + c] =
                    make_float2(acc[w][tn][2], acc[w][tn][3]);
        }
    }
}

// ---------------------------------------------------------------------------
// A-row gather: A[b, kk] = [ x(CIN) | h_or_zh(64) | Gx(CIN) | Gh_or_Gzh(64) ]
// ---------------------------------------------------------------------------
template<int CIN, int MODE>
__device__ __forceinline__ float gatherA(const float* __restrict__ xext,
                                         int b, int n, int t, int kk) {
    long hoff = ((long)b*NN + n)*64;
    if (CIN == 2) {
        if (kk >= 132) return 0.0f;
        long xoff = ((long)b*TT + t)*NN*2 + (long)n*2;
        if (kk < 2)   return xext[xoff + kk];
        if (kk < 66)  return (MODE ? g_zh0 : g_h0)[hoff + (kk - 2)];
        if (kk < 68)  return g_Gx2[xoff + (kk - 66)];
        return (MODE ? g_Gzh0 : g_Gh0)[hoff + (kk - 68)];
    } else {
        long xoff = ((long)b*TT + t)*NN*64 + (long)n*64;
        if (kk < 64)  return g_seq0[xoff + kk];
        if (kk < 128) return (MODE ? g_zh1 : g_h1)[hoff + (kk - 64)];
        if (kk < 192) return g_Gxall[xoff + (kk - 128)];
        return (MODE ? g_Gzh1 : g_Gh1)[hoff + (kk - 192)];
    }
}

// ---------------------------------------------------------------------------
// Gate GEMM: tile 64b x 64o, 128 threads, 8b x 4o per thread. A as [kk][b].
// grid (NN, 2 bhalf, 2 ohalf).  oh=0: z -> zh = z*h.  oh=1: r.
// ---------------------------------------------------------------------------
template<int CIN>
__global__ void __launch_bounds__(128, 8) gate_k(const float* __restrict__ xext, int t) {
    constexpr int KD  = 2*CIN + 2*DOUT;
    constexpr int NKT = (KD + 31) / 32;
    const float* W    = (CIN == 2) ? g_Wg0 : g_Wg1;
    const float* bias = (CIN == 2) ? g_bg0 : g_bg1;
    const float* hbuf = (CIN == 2) ? g_h0  : g_h1;
    float* zhbuf      = (CIN == 2) ? g_zh0 : g_zh1;
    float* rbuf       = (CIN == 2) ? g_r0  : g_r1;

    int n  = blockIdx.x;
    int bh = blockIdx.y;
    int oh = blockIdx.z;
    int tid = threadIdx.x;
    int tx = tid & 15;
    int ty = tid >> 4;

    __shared__ float As[32][68];
    __shared__ float Ws[32][68];

    unsigned long long acc2[8][2];
#pragma unroll
    for (int i = 0; i < 8; i++) { acc2[i][0] = 0ull; acc2[i][1] = 0ull; }

    for (int kt = 0; kt < NKT; kt++) {
        int k0 = kt * 32;
#pragma unroll
        for (int j = 0; j < 16; j++) {
            int lin = tid + j*128;
            int kl = lin & 31;
            int b  = lin >> 5;
            As[kl][b] = gatherA<CIN,0>(xext, bh*64 + b, n, t, k0 + kl);
        }
#pragma unroll
        for (int j = 0; j < 4; j++) {
            int lin = tid + j*128;
            int c4  = lin & 15;
            int row = lin >> 4;
            int kk = k0 + row;
            float4 v = make_float4(0.f, 0.f, 0.f, 0.f);
            if (kk < KD)
                v = *(const float4*)&W[((long)n*KD + kk)*128 + oh*64 + c4*4];
            *(float4*)&Ws[row][c4*4] = v;
        }
        __syncthreads();
#pragma unroll
        for (int k = 0; k < 32; k++) {
            float4 aLo = *(const float4*)&As[k][ty*8];
            float4 aHi = *(const float4*)&As[k][ty*8 + 4];
            ulonglong2 w2 = *(const ulonglong2*)&Ws[k][tx*4];
            float av[8] = {aLo.x, aLo.y, aLo.z, aLo.w,
                           aHi.x, aHi.y, aHi.z, aHi.w};
#pragma unroll
            for (int i = 0; i < 8; i++) {
                unsigned long long ad = pk2(av[i], av[i]);
                acc2[i][0] = ffma2(ad, w2.x, acc2[i][0]);
                acc2[i][1] = ffma2(ad, w2.y, acc2[i][1]);
            }
        }
        __syncthreads();
    }

    float4 bv = *(const float4*)&bias[n*128 + oh*64 + tx*4];
#pragma unroll
    for (int i = 0; i < 8; i++) {
        int b = bh*64 + ty*8 + i;
        long hb = ((long)b*NN + n)*64 + tx*4;
        float v0, v1, v2, v3;
        unpk2(acc2[i][0], v0, v1);
        unpk2(acc2[i][1], v2, v3);
        v0 = sigm(v0 + bv.x); v1 = sigm(v1 + bv.y);
        v2 = sigm(v2 + bv.z); v3 = sigm(v3 + bv.w);
        if (oh == 0) {
            float4 hv = *(const float4*)&hbuf[hb];
            *(float4*)&zhbuf[hb] = make_float4(v0*hv.x, v1*hv.y, v2*hv.z, v3*hv.w);
        } else {
            *(float4*)&rbuf[hb] = make_float4(v0, v1, v2, v3);
        }
    }
}

// ---------------------------------------------------------------------------
// Candidate GEMM (NO=64) + GRU update. tile 64b x 64o, grid (NN, 2).
// ---------------------------------------------------------------------------
template<int CIN>
__global__ void __launch_bounds__(128, 8) cand_k(const float* __restrict__ xext, int t,
                                                 float* __restrict__ curOut,
                                                 float* __restrict__ lastOut) {
    constexpr int KD  = 2*CIN + 2*DOUT;
    constexpr int NKT = (KD + 31) / 32;
    const float* W    = (CIN == 2) ? g_Wu0 : g_Wu1;
    const float* bias = (CIN == 2) ? g_bu0 : g_bu1;
    float* hbuf       = (CIN == 2) ? g_h0  : g_h1;
    const float* rbuf = (CIN == 2) ? g_r0  : g_r1;

    int n  = blockIdx.x;
    int bh = blockIdx.y;
    int tid = threadIdx.x;
    int tx = tid & 15;
    int ty = tid >> 4;

    __shared__ float As[32][68];
    __shared__ float Ws[32][68];

    unsigned long long acc2[8][2];
#pragma unroll
    for (int i = 0; i < 8; i++) { acc2[i][0] = 0ull; acc2[i][1] = 0ull; }

    for (int kt = 0; kt < NKT; kt++) {
        int k0 = kt * 32;
#pragma unroll
        for (int j = 0; j < 16; j++) {
            int lin = tid + j*128;
            int kl = lin & 31;
            int b  = lin >> 5;
            As[kl][b] = gatherA<CIN,1>(xext, bh*64 + b, n, t, k0 + kl);
        }
#pragma unroll
        for (int j = 0; j < 4; j++) {
            int lin = tid + j*128;
            int c4  = lin & 15;
            int row = lin >> 4;
            int kk = k0 + row;
            float4 v = make_float4(0.f, 0.f, 0.f, 0.f);
            if (kk < KD)
                v = *(const float4*)&W[((long)n*KD + kk)*64 + c4*4];
            *(float4*)&Ws[row][c4*4] = v;
        }
        __syncthreads();
#pragma unroll
        for (int k = 0; k < 32; k++) {
            float4 aLo = *(const float4*)&As[k][ty*8];
            float4 aHi = *(const float4*)&As[k][ty*8 + 4];
            ulonglong2 w2 = *(const ulonglong2*)&Ws[k][tx*4];
            float av[8] = {aLo.x, aLo.y, aLo.z, aLo.w,
                           aHi.x, aHi.y, aHi.z, aHi.w};
#pragma unroll
            for (int i = 0; i < 8; i++) {
                unsigned long long ad = pk2(av[i], av[i]);
                acc2[i][0] = ffma2(ad, w2.x, acc2[i][0]);
                acc2[i][1] = ffma2(ad, w2.y, acc2[i][1]);
            }
        }
        __syncthreads();
    }

    float4 bv = *(const float4*)&bias[n*64 + tx*4];
#pragma unroll
    for (int i = 0; i < 8; i++) {
        int b = bh*64 + ty*8 + i;
        long hb = ((long)b*NN + n)*64 + tx*4;
        float c0, c1, c2, c3;
        unpk2(acc2[i][0], c0, c1);
        unpk2(acc2[i][1], c2, c3);
        c0 = tanhf(c0 + bv.x); c1 = tanhf(c1 + bv.y);
        c2 = tanhf(c2 + bv.z); c3 = tanhf(c3 + bv.w);
        float4 rv = *(const float4*)&rbuf[hb];
        float4 hv = *(const float4*)&hbuf[hb];
        float4 o;
        o.x = rv.x*hv.x + (1.0f - rv.x)*c0;
        o.y = rv.y*hv.y + (1.0f - rv.y)*c1;
        o.z = rv.z*hv.z + (1.0f - rv.z)*c2;
        o.w = rv.w*hv.w + (1.0f - rv.w)*c3;
        *(float4*)&hbuf[hb] = o;
        float* seq = (CIN == 2) ? g_seq0 : curOut;
        *(float4*)&seq[((long)(b*TT + t))*NN*DOUT + (long)n*DOUT + tx*4] = o;
        if (lastOut) *(float4*)&lastOut[hb] = o;
    }
}

// ---------------------------------------------------------------------------
// Host driver — graph-capturable. Streams: layer0 on sA, Gx1 on sC, layer1 on sB.
// ---------------------------------------------------------------------------
extern "C" void kernel_launch(void* const* d_in, const int* in_sizes, int n_in,
                              void* d_out, int out_size) {
    const float* x    = (const float*)d_in[0];
    const float* init = (const float*)d_in[1];
    const float* E    = (const float*)d_in[2];
    const float* adj  = (const float*)d_in[3];
    const float* wg0  = (const float*)d_in[4];
    const float* bg0  = (const float*)d_in[5];
    const float* wu0  = (const float*)d_in[6];
    const float* bu0  = (const float*)d_in[7];
    const float* wg1  = (const float*)d_in[8];
    const float* bg1  = (const float*)d_in[9];
    const float* wu1  = (const float*)d_in[10];
    const float* bu1  = (const float*)d_in[11];

    float* out      = (float*)d_out;
    float* lastBase = out + (long)CURSZ;

    static cudaStream_t sA = nullptr, sB = nullptr, sC = nullptr;
    static cudaEvent_t eFork = nullptr, eA = nullptr, eB = nullptr;
    static cudaEvent_t e0[TT], eC[TT];
    if (!sA) {
        cudaStreamCreateWithFlags(&sA, cudaStreamNonBlocking);
        cudaStreamCreateWithFlags(&sB, cudaStreamNonBlocking);
        cudaStreamCreateWithFlags(&sC, cudaStreamNonBlocking);
        cudaEventCreateWithFlags(&eFork, cudaEventDisableTiming);
        cudaEventCreateWithFlags(&eA, cudaEventDisableTiming);
        cudaEventCreateWithFlags(&eB, cudaEventDisableTiming);
        for (int t = 0; t < TT; t++) {
            cudaEventCreateWithFlags(&e0[t], cudaEventDisableTiming);
            cudaEventCreateWithFlags(&eC[t], cudaEventDisableTiming);
        }
    }

    // ---- prelude on the capture (default) stream ----
    prep_all<<<(unsigned)((C7 + 255) / 256), 256>>>(E, wg0, wu0, wg1, wu1,
                                                    bg0, bu0, bg1, bu1);
    prep_adjB<<<(NNP*NNP + 255) / 256, 256>>>(adj);
    init_h<<<(BND + 255) / 256, 256>>>(init, 0);
    init_h<<<(BND + 255) / 256, 256>>>(init, 1);
    graph_x2_all<<<dim3(5, BT/64), 256>>>(adj, x);

    cudaEventRecord(eFork, 0);
    cudaStreamWaitEvent(sA, eFork, 0);
    cudaStreamWaitEvent(sB, eFork, 0);
    cudaStreamWaitEvent(sC, eFork, 0);

    dim3 gGrid(5, BB/2);   // graph64_mma: 320 blocks x 256 thr, 2 batches each

    // ---- layer 0 on sA ----
    for (int t = 0; t < TT; t++) {
        graph64_mma<<<gGrid, 256, 0, sA>>>(0, t, 0);                    // Gh0
        gate_k<2><<<dim3(NN,2,2), 128, 0, sA>>>(x, t);                  // z*h, r
        graph64_mma<<<gGrid, 256, 0, sA>>>(1, t, 1);                    // Gzh0
        cand_k<2><<<dim3(NN,2), 128, 0, sA>>>(x, t, nullptr,
                        (t == TT-1) ? lastBase : nullptr);              // h0', seq0[t]
        cudaEventRecord(e0[t], sA);
    }
    // ---- Gx1 producer on sC (gated on seq0[t], full per-t buffering) ----
    for (int t = 0; t < TT; t++) {
        cudaStreamWaitEvent(sC, e0[t], 0);
        graph64_mma<<<gGrid, 256, 0, sC>>>(2, t, 2);                    // Gxall[t]
        cudaEventRecord(eC[t], sC);
    }
    // ---- layer 1 on sB ----
    for (int t = 0; t < TT; t++) {
        graph64_mma<<<gGrid, 256, 0, sB>>>(3, t, 3);                    // Gh1 (dep: h1 only)
        cudaStreamWaitEvent(sB, eC[t], 0);                              // Gxall[t], seq0[t]
        gate_k<64><<<dim3(NN,2,2), 128, 0, sB>>>(nullptr, t);
        graph64_mma<<<gGrid, 256, 0, sB>>>(4, t, 4);                    // Gzh1
        cand_k<64><<<dim3(NN,2), 128, 0, sB>>>(nullptr, t, out,
                        (t == TT-1) ? lastBase + BND : nullptr);
    }

    cudaEventRecord(eA, sA);
    cudaEventRecord(eB, sB);
    cudaStreamWaitEvent(0, eA, 0);
    cudaStreamWaitEvent(0, eB, 0);
}

// round 11
// speedup vs baseline: 1.2771x; 1.0911x over previous
#include <cuda_runtime.h>
#include <cuda_bf16.h>
#include <math.h>
#include <cstdint>

// Problem constants
#define NN   307
#define TT   12
#define BB   128
#define DIN  2
#define DOUT 64
#define DE   10
#define NNP  320                  // padded node dim (k-dim for mma, mult of 16)

#define BND   (BB*NN*DOUT)        // 2,514,944
#define CURSZ (BB*TT*NN*DOUT)     // 30,179,328
#define BT    (BB*TT)             // 1536

// ---------------------------------------------------------------------------
// Device scratch
// ---------------------------------------------------------------------------
__device__ float g_Wg0[NN*132*128];
__device__ float g_Wu0[NN*132*64];
__device__ float g_Wg1[NN*256*128];
__device__ float g_Wu1[NN*256*64];
__device__ float g_bg0[NN*128];
__device__ float g_bu0[NN*64];
__device__ float g_bg1[NN*128];
__device__ float g_bu1[NN*64];

__device__ __nv_bfloat16 g_adjH[NNP*NNP];   // adj [n][m] bf16 hi plane, zero-padded
__device__ __nv_bfloat16 g_adjL[NNP*NNP];   // adj [n][m] bf16 lo plane

// per-layer state (layers run concurrently on separate streams)
__device__ float g_h0  [BND];
__device__ float g_zh0 [BND];
__device__ float g_r0  [BND];
__device__ float g_Gh0 [BND];
__device__ float g_Gzh0[BND];
__device__ float g_h1  [BND];
__device__ float g_zh1 [BND];
__device__ float g_r1  [BND];
__device__ float g_Gh1 [BND];
__device__ float g_Gzh1[BND];

__device__ float g_Gx2 [BT*NN*DIN];   // adj @ x (layer0, all t) [B,T,N,2]
__device__ float g_Gxall[CURSZ];      // adj @ seq0[t] for all t [B,T,N,64]
__device__ float g_seq0[CURSZ];       // layer0 output sequence [B,T,N,64]

__device__ __forceinline__ float sigm(float v) { return 1.0f / (1.0f + expf(-v)); }

// packed fp32x2 helpers (GEMMs)
__device__ __forceinline__ unsigned long long pk2(float x, float y) {
    unsigned long long r;
    asm("mov.b64 %0, {%1, %2};" : "=l"(r) : "f"(x), "f"(y));
    return r;
}
__device__ __forceinline__ unsigned long long ffma2(unsigned long long a,
                                                    unsigned long long b,
                                                    unsigned long long c) {
    unsigned long long d;
    asm("fma.rn.f32x2 %0, %1, %2, %3;" : "=l"(d) : "l"(a), "l"(b), "l"(c));
    return d;
}
__device__ __forceinline__ void unpk2(unsigned long long v, float& lo, float& hi) {
    asm("mov.b64 {%0, %1}, %2;" : "=f"(lo), "=f"(hi) : "l"(v));
}

// bf16 mma.sync m16n8k16
__device__ __forceinline__ void mma_bf16(float* c, const uint32_t* a,
                                         uint32_t b0, uint32_t b1) {
    asm volatile(
        "mma.sync.aligned.m16n8k16.row.col.f32.bf16.bf16.f32 "
        "{%0,%1,%2,%3}, {%4,%5,%6,%7}, {%8,%9}, {%0,%1,%2,%3};"
        : "+f"(c[0]), "+f"(c[1]), "+f"(c[2]), "+f"(c[3])
        : "r"(a[0]), "r"(a[1]), "r"(a[2]), "r"(a[3]), "r"(b0), "r"(b1));
}

// ---------------------------------------------------------------------------
// prep kernels
// ---------------------------------------------------------------------------
#define S_WG0 (132*128)
#define S_WU0 (132*64)
#define S_WG1 (256*128)
#define S_WU1 (256*64)
#define C0 ((long)NN*S_WG0)
#define C1 (C0 + (long)NN*S_WU0)
#define C2 (C1 + (long)NN*S_WG1)
#define C3 (C2 + (long)NN*S_WU1)
#define C4 (C3 + (long)NN*128)
#define C5 (C4 + (long)NN*64)
#define C6 (C5 + (long)NN*128)
#define C7 (C6 + (long)NN*64)

__global__ void prep_all(const float* __restrict__ E,
                         const float* __restrict__ wg0, const float* __restrict__ wu0,
                         const float* __restrict__ wg1, const float* __restrict__ wu1,
                         const float* __restrict__ bg0, const float* __restrict__ bu0,
                         const float* __restrict__ bg1, const float* __restrict__ bu1) {
    long idx = (long)blockIdx.x * blockDim.x + threadIdx.x;
    if (idx >= C7) return;
    const float* pool; float* out; long loc; int S;
    if      (idx < C0) { pool = wg0; out = g_Wg0; loc = idx;      S = S_WG0; }
    else if (idx < C1) { pool = wu0; out = g_Wu0; loc = idx - C0; S = S_WU0; }
    else if (idx < C2) { pool = wg1; out = g_Wg1; loc = idx - C1; S = S_WG1; }
    else if (idx < C3) { pool = wu1; out = g_Wu1; loc = idx - C2; S = S_WU1; }
    else if (idx < C4) { pool = bg0; out = g_bg0; loc = idx - C3; S = 128;   }
    else if (idx < C5) { pool = bu0; out = g_bu0; loc = idx - C4; S = 64;    }
    else if (idx < C6) { pool = bg1; out = g_bg1; loc = idx - C5; S = 128;   }
    else               { pool = bu1; out = g_bu1; loc = idx - C6; S = 64;    }
    int n = (int)(loc / S);
    long j = loc - (long)n * S;
    float acc = 0.0f;
#pragma unroll
    for (int d = 0; d < DE; d++)
        acc += E[n*DE + d] * pool[(long)d*S + j];
    out[loc] = acc;
}

// adj -> bf16 hi/lo planes, [n][m] layout, zero-padded to 320x320
__global__ void prep_adjB(const float* __restrict__ adj) {
    int i = blockIdx.x * blockDim.x + threadIdx.x;
    if (i >= NNP*NNP) return;
    int n = i / NNP, m = i - n*NNP;
    float v = (n < NN && m < NN) ? adj[(long)n*NN + m] : 0.0f;
    __nv_bfloat16 h = __float2bfloat16(v);
    __nv_bfloat16 l = __float2bfloat16(v - __bfloat162float(h));
    g_adjH[i] = h;
    g_adjL[i] = l;
}

__global__ void init_h(const float* __restrict__ init, int l) {
    int i = blockIdx.x * blockDim.x + threadIdx.x;
    if (i < BND) {
        float v = init[(long)l*BND + i];
        if (l == 0) g_h0[i] = v; else g_h1[i] = v;
    }
}

// ---------------------------------------------------------------------------
// adj @ x for all timesteps (layer0, 2 channels): one launch, f32 (tiny)
// ---------------------------------------------------------------------------
__global__ void __launch_bounds__(256) graph_x2_all(const float* __restrict__ adj,
                                                    const float* __restrict__ x) {
    int n0  = blockIdx.x * 64;
    int bt0 = blockIdx.y * 64;
    int tid = threadIdx.x;
    int tx  = tid & 15;
    int ty  = tid >> 4;

    __shared__ float adjs[32][65];
    __shared__ float xs[64][65];

    float acc[4][4][2] = {};

    for (int m0 = 0; m0 < NN; m0 += 32) {
#pragma unroll
        for (int j = 0; j < 8; j++) {
            int lin = tid + j*256;
            int nl = lin >> 5, ml = lin & 31;
            int n = n0 + nl, m = m0 + ml;
            adjs[ml][nl] = (n < NN && m < NN) ? adj[(long)n*NN + m] : 0.0f;
        }
#pragma unroll
        for (int j = 0; j < 16; j++) {
            int lin = tid + j*256;
            int mc = lin & 63;
            int bt = lin >> 6;
            int m = m0 + (mc >> 1);
            xs[mc][bt] = (m < NN) ? x[((long)(bt0 + bt)*NN + m)*2 + (mc & 1)] : 0.0f;
        }
        __syncthreads();
#pragma unroll
        for (int ml = 0; ml < 32; ml++) {
            float a0 = adjs[ml][ty*4+0];
            float a1 = adjs[ml][ty*4+1];
            float a2 = adjs[ml][ty*4+2];
            float a3 = adjs[ml][ty*4+3];
#pragma unroll
            for (int jj = 0; jj < 4; jj++) {
                float x0 = xs[ml*2+0][tx*4+jj];
                float x1 = xs[ml*2+1][tx*4+jj];
                acc[0][jj][0] += a0*x0; acc[0][jj][1] += a0*x1;
                acc[1][jj][0] += a1*x0; acc[1][jj][1] += a1*x1;
                acc[2][jj][0] += a2*x0; acc[2][jj][1] += a2*x1;
                acc[3][jj][0] += a3*x0; acc[3][jj][1] += a3*x1;
            }
        }
        __syncthreads();
    }
#pragma unroll
    for (int i = 0; i < 4; i++) {
        int n = n0 + ty*4 + i;
        if (n >= NN) continue;
#pragma unroll
        for (int jj = 0; jj < 4; jj++) {
            int bt = bt0 + tx*4 + jj;
            *(float2*)&g_Gx2[((long)bt*NN + n)*2] =
                make_float2(acc[i][jj][0], acc[i][jj][1]);
        }
    }
}

// ---------------------------------------------------------------------------
// Graph propagation via bf16 split mma (R8 version, 1 batch/block).
// Per block: 64 nodes x 64 channels x 1 batch; 8 warps as 4(m16) x 2(n32).
// grid (5, 128).  srcsel: 0=h0, 1=zh0, 2=seq0[t], 3=h1, 4=zh1
// dstsel: 0=Gh0, 1=Gzh0, 2=Gxall[t], 3=Gh1, 4=Gzh1
// ---------------------------------------------------------------------------
__global__ void __launch_bounds__(256) graph64_mma(int srcsel, int t, int dstsel) {
    const float* src; long sstride = (long)NN*DOUT;
    switch (srcsel) {
        case 0:  src = g_h0;  break;
        case 1:  src = g_zh0; break;
        case 2:  src = g_seq0 + (long)t*NN*DOUT; sstride = (long)TT*NN*DOUT; break;
        case 3:  src = g_h1;  break;
        default: src = g_zh1; break;
    }
    float* dst; long dstride = (long)NN*DOUT;
    switch (dstsel) {
        case 0:  dst = g_Gh0;  break;
        case 1:  dst = g_Gzh0; break;
        case 2:  dst = g_Gxall + (long)t*NN*DOUT; dstride = (long)TT*NN*DOUT; break;
        case 3:  dst = g_Gh1;  break;
        default: dst = g_Gzh1; break;
    }

    int n0  = blockIdx.x * 64;
    int b   = blockIdx.y;
    int tid = threadIdx.x;
    int lane = tid & 31;
    int wid  = tid >> 5;
    int wm = wid & 3;            // m16 tile: rows n0 + wm*16
    int wn = wid >> 2;           // n32 tile: cols wn*32

    __shared__ __nv_bfloat16 Ah[64][20], Al[64][20];   // A: [n][m16]
    __shared__ __nv_bfloat16 Bh[64][20], Bl[64][20];   // B: [c][m16]

    float acc[4][4];
#pragma unroll
    for (int i = 0; i < 4; i++)
#pragma unroll
        for (int j = 0; j < 4; j++) acc[i][j] = 0.0f;

    const float* sb = src + (long)b * sstride;
    int bc = tid & 63;           // B fill: channel
    int bm = (tid >> 6) * 4;     // B fill: first of 4 k rows

    for (int m0 = 0; m0 < NNP; m0 += 16) {
        // A fill: u32 = 2 bf16 per plane
#pragma unroll
        for (int j = 0; j < 2; j++) {
            int lin = tid + j*256;
            int nl = lin >> 3, kp = lin & 7;
            long src_off = (long)(n0 + nl)*NNP + m0 + kp*2;
            *(uint32_t*)&Ah[nl][kp*2] = *(const uint32_t*)&g_adjH[src_off];
            *(uint32_t*)&Al[nl][kp*2] = *(const uint32_t*)&g_adjL[src_off];
        }
        // B fill: 16k x 64c from f32 src, split into hi/lo
#pragma unroll
        for (int i = 0; i < 4; i++) {
            int ml = bm + i;
            int m  = m0 + ml;
            float v = (m < NN) ? sb[(long)m*DOUT + bc] : 0.0f;
            __nv_bfloat16 h = __float2bfloat16(v);
            __nv_bfloat16 l = __float2bfloat16(v - __bfloat162float(h));
            Bh[bc][ml] = h;
            Bl[bc][ml] = l;
        }
        __syncthreads();

        uint32_t a_h[4], a_l[4];
#pragma unroll
        for (int j = 0; j < 4; j++) {
            int row = wm*16 + (lane >> 2) + (j & 1)*8;
            int kp  = (lane & 3)*2 + (j & 2)*4;
            a_h[j] = *(const uint32_t*)&Ah[row][kp];
            a_l[j] = *(const uint32_t*)&Al[row][kp];
        }
#pragma unroll
        for (int tn = 0; tn < 4; tn++) {
            int cc  = wn*32 + tn*8 + (lane >> 2);
            int k0p = (lane & 3)*2;
            uint32_t b_h0 = *(const uint32_t*)&Bh[cc][k0p];
            uint32_t b_h1 = *(const uint32_t*)&Bh[cc][k0p + 8];
            uint32_t b_l0 = *(const uint32_t*)&Bl[cc][k0p];
            uint32_t b_l1 = *(const uint32_t*)&Bl[cc][k0p + 8];
            mma_bf16(acc[tn], a_h, b_h0, b_h1);
            mma_bf16(acc[tn], a_h, b_l0, b_l1);
            mma_bf16(acc[tn], a_l, b_h0, b_h1);
        }
        __syncthreads();
    }

    long db = (long)b * dstride;
#pragma unroll
    for (int tn = 0; tn < 4; tn++) {
        int n = n0 + wm*16 + (lane >> 2);
        int c = wn*32 + tn*8 + (lane & 3)*2;
        if (n < NN)
            *(float2*)&dst[db + (long)n*DOUT + c] =
                make_float2(acc[tn][0], acc[tn][1]);
        if (n + 8 < NN)
            *(float2*)&dst[db + (long)(n + 8)*DOUT + c] =
                make_float2(acc[tn][2], acc[tn][3]);
    }
}

// ---------------------------------------------------------------------------
// A-row gather: A[b, kk] = [ x(CIN) | h_or_zh(64) | Gx(CIN) | Gh_or_Gzh(64) ]
// ---------------------------------------------------------------------------
template<int CIN, int MODE>
__device__ __forceinline__ float gatherA(const float* __restrict__ xext,
                                         int b, int n, int t, int kk) {
    long hoff = ((long)b*NN + n)*64;
    if (CIN == 2) {
        if (kk >= 132) return 0.0f;
        long xoff = ((long)b*TT + t)*NN*2 + (long)n*2;
        if (kk < 2)   return xext[xoff + kk];
        if (kk < 66)  return (MODE ? g_zh0 : g_h0)[hoff + (kk - 2)];
        if (kk < 68)  return g_Gx2[xoff + (kk - 66)];
        return (MODE ? g_Gzh0 : g_Gh0)[hoff + (kk - 68)];
    } else {
        long xoff = ((long)b*TT + t)*NN*64 + (long)n*64;
        if (kk < 64)  return g_seq0[xoff + kk];
        if (kk < 128) return (MODE ? g_zh1 : g_h1)[hoff + (kk - 64)];
        if (kk < 192) return g_Gxall[xoff + (kk - 128)];
        return (MODE ? g_Gzh1 : g_Gh1)[hoff + (kk - 192)];
    }
}

// ---------------------------------------------------------------------------
// Gate GEMM, oh-merged: tile 64b x 128o, 256 threads, 8b x 4o per thread.
// A gathered ONCE for both z and r halves. grid (NN, 2 bhalf).
// o<64: z -> zh = z*h.  o>=64: r.
// ---------------------------------------------------------------------------
template<int CIN>
__global__ void __launch_bounds__(256, 4) gate_k(const float* __restrict__ xext, int t) {
    constexpr int KD  = 2*CIN + 2*DOUT;
    constexpr int NKT = (KD + 31) / 32;
    const float* W    = (CIN == 2) ? g_Wg0 : g_Wg1;
    const float* bias = (CIN == 2) ? g_bg0 : g_bg1;
    const float* hbuf = (CIN == 2) ? g_h0  : g_h1;
    float* zhbuf      = (CIN == 2) ? g_zh0 : g_zh1;
    float* rbuf       = (CIN == 2) ? g_r0  : g_r1;

    int n  = blockIdx.x;
    int bh = blockIdx.y;
    int tid = threadIdx.x;
    int tx = tid & 31;          // o group (4 cols, 32 groups = 128 o)
    int ty = tid >> 5;          // b group (8 rows, 8 groups = 64 b)

    __shared__ float As[32][68];    // [kk][b]
    __shared__ float Ws[32][132];   // [kk][o], pad 132

    unsigned long long acc2[8][2];
#pragma unroll
    for (int i = 0; i < 8; i++) { acc2[i][0] = 0ull; acc2[i][1] = 0ull; }

    for (int kt = 0; kt < NKT; kt++) {
        int k0 = kt * 32;
        // A: 64b x 32kk gathered once (2048 / 256 = 8)
#pragma unroll
        for (int j = 0; j < 8; j++) {
            int lin = tid + j*256;
            int kl = lin & 31;
            int b  = lin >> 5;
            As[kl][b] = gatherA<CIN,0>(xext, bh*64 + b, n, t, k0 + kl);
        }
        // W: 32kk x 128o (1024 float4 / 256 = 4)
#pragma unroll
        for (int j = 0; j < 4; j++) {
            int lin = tid + j*256;
            int c4  = lin & 31;
            int row = lin >> 5;
            int kk = k0 + row;
            float4 v = make_float4(0.f, 0.f, 0.f, 0.f);
            if (kk < KD)
                v = *(const float4*)&W[((long)n*KD + kk)*128 + c4*4];
            *(float4*)&Ws[row][c4*4] = v;
        }
        __syncthreads();
#pragma unroll
        for (int k = 0; k < 32; k++) {
            float4 aLo = *(const float4*)&As[k][ty*8];
            float4 aHi = *(const float4*)&As[k][ty*8 + 4];
            ulonglong2 w2 = *(const ulonglong2*)&Ws[k][tx*4];
            float av[8] = {aLo.x, aLo.y, aLo.z, aLo.w,
                           aHi.x, aHi.y, aHi.z, aHi.w};
#pragma unroll
            for (int i = 0; i < 8; i++) {
                unsigned long long ad = pk2(av[i], av[i]);
                acc2[i][0] = ffma2(ad, w2.x, acc2[i][0]);
                acc2[i][1] = ffma2(ad, w2.y, acc2[i][1]);
            }
        }
        __syncthreads();
    }

    int o0 = tx*4;                       // 0..124
    float4 bv = *(const float4*)&bias[n*128 + o0];
    bool isZ = (o0 < 64);
    int oc = isZ ? o0 : (o0 - 64);       // channel within the 64-wide output
#pragma unroll
    for (int i = 0; i < 8; i++) {
        int b = bh*64 + ty*8 + i;
        long hb = ((long)b*NN + n)*64 + oc;
        float v0, v1, v2, v3;
        unpk2(acc2[i][0], v0, v1);
        unpk2(acc2[i][1], v2, v3);
        v0 = sigm(v0 + bv.x); v1 = sigm(v1 + bv.y);
        v2 = sigm(v2 + bv.z); v3 = sigm(v3 + bv.w);
        if (isZ) {
            float4 hv = *(const float4*)&hbuf[hb];
            *(float4*)&zhbuf[hb] = make_float4(v0*hv.x, v1*hv.y, v2*hv.z, v3*hv.w);
        } else {
            *(float4*)&rbuf[hb] = make_float4(v0, v1, v2, v3);
        }
    }
}

// ---------------------------------------------------------------------------
// Candidate GEMM (NO=64) + GRU update. tile 64b x 64o, grid (NN, 2).
// ---------------------------------------------------------------------------
template<int CIN>
__global__ void __launch_bounds__(128, 8) cand_k(const float* __restrict__ xext, int t,
                                                 float* __restrict__ curOut,
                                                 float* __restrict__ lastOut) {
    constexpr int KD  = 2*CIN + 2*DOUT;
    constexpr int NKT = (KD + 31) / 32;
    const float* W    = (CIN == 2) ? g_Wu0 : g_Wu1;
    const float* bias = (CIN == 2) ? g_bu0 : g_bu1;
    float* hbuf       = (CIN == 2) ? g_h0  : g_h1;
    const float* rbuf = (CIN == 2) ? g_r0  : g_r1;

    int n  = blockIdx.x;
    int bh = blockIdx.y;
    int tid = threadIdx.x;
    int tx = tid & 15;
    int ty = tid >> 4;

    __shared__ float As[32][68];
    __shared__ float Ws[32][68];

    unsigned long long acc2[8][2];
#pragma unroll
    for (int i = 0; i < 8; i++) { acc2[i][0] = 0ull; acc2[i][1] = 0ull; }

    for (int kt = 0; kt < NKT; kt++) {
        int k0 = kt * 32;
#pragma unroll
        for (int j = 0; j < 16; j++) {
            int lin = tid + j*128;
            int kl = lin & 31;
            int b  = lin >> 5;
            As[kl][b] = gatherA<CIN,1>(xext, bh*64 + b, n, t, k0 + kl);
        }
#pragma unroll
        for (int j = 0; j < 4; j++) {
            int lin = tid + j*128;
            int c4  = lin & 15;
            int row = lin >> 4;
            int kk = k0 + row;
            float4 v = make_float4(0.f, 0.f, 0.f, 0.f);
            if (kk < KD)
                v = *(const float4*)&W[((long)n*KD + kk)*64 + c4*4];
            *(float4*)&Ws[row][c4*4] = v;
        }
        __syncthreads();
#pragma unroll
        for (int k = 0; k < 32; k++) {
            float4 aLo = *(const float4*)&As[k][ty*8];
            float4 aHi = *(const float4*)&As[k][ty*8 + 4];
            ulonglong2 w2 = *(const ulonglong2*)&Ws[k][tx*4];
            float av[8] = {aLo.x, aLo.y, aLo.z, aLo.w,
                           aHi.x, aHi.y, aHi.z, aHi.w};
#pragma unroll
            for (int i = 0; i < 8; i++) {
                unsigned long long ad = pk2(av[i], av[i]);
                acc2[i][0] = ffma2(ad, w2.x, acc2[i][0]);
                acc2[i][1] = ffma2(ad, w2.y, acc2[i][1]);
            }
        }
        __syncthreads();
    }

    float4 bv = *(const float4*)&bias[n*64 + tx*4];
#pragma unroll
    for (int i = 0; i < 8; i++) {
        int b = bh*64 + ty*8 + i;
        long hb = ((long)b*NN + n)*64 + tx*4;
        float c0, c1, c2, c3;
        unpk2(acc2[i][0], c0, c1);
        unpk2(acc2[i][1], c2, c3);
        c0 = tanhf(c0 + bv.x); c1 = tanhf(c1 + bv.y);
        c2 = tanhf(c2 + bv.z); c3 = tanhf(c3 + bv.w);
        float4 rv = *(const float4*)&rbuf[hb];
        float4 hv = *(const float4*)&hbuf[hb];
        float4 o;
        o.x = rv.x*hv.x + (1.0f - rv.x)*c0;
        o.y = rv.y*hv.y + (1.0f - rv.y)*c1;
        o.z = rv.z*hv.z + (1.0f - rv.z)*c2;
        o.w = rv.w*hv.w + (1.0f - rv.w)*c3;
        *(float4*)&hbuf[hb] = o;
        float* seq = (CIN == 2) ? g_seq0 : curOut;
        *(float4*)&seq[((long)(b*TT + t))*NN*DOUT + (long)n*DOUT + tx*4] = o;
        if (lastOut) *(float4*)&lastOut[hb] = o;
    }
}

// ---------------------------------------------------------------------------
// Host driver — graph-capturable. Streams: layer0 on sA, Gx on sC, layer1 on sB.
// ---------------------------------------------------------------------------
extern "C" void kernel_launch(void* const* d_in, const int* in_sizes, int n_in,
                              void* d_out, int out_size) {
    const float* x    = (const float*)d_in[0];
    const float* init = (const float*)d_in[1];
    const float* E    = (const float*)d_in[2];
    const float* adj  = (const float*)d_in[3];
    const float* wg0  = (const float*)d_in[4];
    const float* bg0  = (const float*)d_in[5];
    const float* wu0  = (const float*)d_in[6];
    const float* bu0  = (const float*)d_in[7];
    const float* wg1  = (const float*)d_in[8];
    const float* bg1  = (const float*)d_in[9];
    const float* wu1  = (const float*)d_in[10];
    const float* bu1  = (const float*)d_in[11];

    float* out      = (float*)d_out;
    float* lastBase = out + (long)CURSZ;

    static cudaStream_t sA = nullptr, sB = nullptr, sC = nullptr;
    static cudaEvent_t eFork = nullptr, eA = nullptr, eB = nullptr;
    static cudaEvent_t e0[TT], eC[TT];
    if (!sA) {
        cudaStreamCreateWithFlags(&sA, cudaStreamNonBlocking);
        cudaStreamCreateWithFlags(&sB, cudaStreamNonBlocking);
        cudaStreamCreateWithFlags(&sC, cudaStreamNonBlocking);
        cudaEventCreateWithFlags(&eFork, cudaEventDisableTiming);
        cudaEventCreateWithFlags(&eA, cudaEventDisableTiming);
        cudaEventCreateWithFlags(&eB, cudaEventDisableTiming);
        for (int t = 0; t < TT; t++) {
            cudaEventCreateWithFlags(&e0[t], cudaEventDisableTiming);
            cudaEventCreateWithFlags(&eC[t], cudaEventDisableTiming);
        }
    }

    // ---- prelude on the capture (default) stream ----
    prep_all<<<(unsigned)((C7 + 255) / 256), 256>>>(E, wg0, wu0, wg1, wu1,
                                                    bg0, bu0, bg1, bu1);
    prep_adjB<<<(NNP*NNP + 255) / 256, 256>>>(adj);
    init_h<<<(BND + 255) / 256, 256>>>(init, 0);
    init_h<<<(BND + 255) / 256, 256>>>(init, 1);
    graph_x2_all<<<dim3(5, BT/64), 256>>>(adj, x);

    cudaEventRecord(eFork, 0);
    cudaStreamWaitEvent(sA, eFork, 0);
    cudaStreamWaitEvent(sB, eFork, 0);
    cudaStreamWaitEvent(sC, eFork, 0);

    dim3 gGrid(5, BB);   // graph64_mma: 640 blocks x 256 thr, 1 batch each

    // ---- layer 0 on sA ----
    for (int t = 0; t < TT; t++) {
        graph64_mma<<<gGrid, 256, 0, sA>>>(0, t, 0);                    // Gh0
        gate_k<2><<<dim3(NN,2), 256, 0, sA>>>(x, t);                    // z*h, r
        graph64_mma<<<gGrid, 256, 0, sA>>>(1, t, 1);                    // Gzh0
        cand_k<2><<<dim3(NN,2), 128, 0, sA>>>(x, t, nullptr,
                        (t == TT-1) ? lastBase : nullptr);              // h0', seq0[t]
        cudaEventRecord(e0[t], sA);
    }
    // ---- Gx producer on sC (gated on seq0[t], fully buffered per t) ----
    for (int t = 0; t < TT; t++) {
        cudaStreamWaitEvent(sC, e0[t], 0);
        graph64_mma<<<gGrid, 256, 0, sC>>>(2, t, 2);                    // Gxall[t]
        cudaEventRecord(eC[t], sC);
    }
    // ---- layer 1 on sB ----
    for (int t = 0; t < TT; t++) {
        graph64_mma<<<gGrid, 256, 0, sB>>>(3, t, 3);                    // Gh1
        cudaStreamWaitEvent(sB, eC[t], 0);                              // Gxall[t], seq0[t]
        gate_k<64><<<dim3(NN,2), 256, 0, sB>>>(nullptr, t);
        graph64_mma<<<gGrid, 256, 0, sB>>>(4, t, 4);                    // Gzh1
        cand_k<64><<<dim3(NN,2), 128, 0, sB>>>(nullptr, t, out,
                        (t == TT-1) ? lastBase + BND : nullptr);
    }

    cudaEventRecord(eA, sA);
    cudaEventRecord(eB, sB);
    cudaStreamWaitEvent(0, eA, 0);
    cudaStreamWaitEvent(0, eB, 0);
}